// round 3
// baseline (speedup 1.0000x reference)
#include <cuda_runtime.h>
#include <math.h>

#define BATCH 1024
#define HID   512
#define VOC   512
#define TSTEPS 64
#define FH    2048   // 4*HID

// -------- persistent device scratch (no allocs allowed) --------
__device__ float g_EProj[VOC * FH];            // embedding @ W_ih^T + bias, 4MB
__device__ float g_h[2][BATCH * HID];          // double-buffered hidden state
__device__ float g_c[BATCH * HID];             // cell state
__device__ unsigned long long g_key[2][BATCH]; // packed (value|~idx) argmax keys

// -------- packed fp32x2 helpers (sm_103a FFMA2 path) --------
__device__ __forceinline__ unsigned long long pack2(float x, float y) {
    unsigned long long r;
    asm("mov.b64 %0, {%1, %2};" : "=l"(r) : "f"(x), "f"(y));
    return r;
}
__device__ __forceinline__ float2 unpack2(unsigned long long v) {
    float2 r;
    asm("mov.b64 {%0, %1}, %2;" : "=f"(r.x), "=f"(r.y) : "l"(v));
    return r;
}
__device__ __forceinline__ void fma2(unsigned long long& d, unsigned long long a,
                                     unsigned long long b) {
    asm("fma.rn.f32x2 %0, %1, %2, %3;" : "=l"(d) : "l"(a), "l"(b), "l"(d));
}
__device__ __forceinline__ float sigf(float x) { return 0.5f * tanhf(0.5f * x) + 0.5f; }

__device__ __forceinline__ unsigned int fmono(float v) {
    unsigned int u = __float_as_uint(v);
    return u ^ ((unsigned int)((int)u >> 31) | 0x80000000u);
}
__device__ __forceinline__ unsigned long long mkkey(float v, int idx) {
    return ((unsigned long long)fmono(v) << 32) | (0xFFFFFFFFu - (unsigned)idx);
}

// ============================================================
// init
// ============================================================
__global__ void __launch_bounds__(256) init_kernel(const float* __restrict__ eh,
                                                   const float* __restrict__ ec) {
    int i = blockIdx.x * blockDim.x + threadIdx.x;
    int stride = gridDim.x * blockDim.x;
    for (int k = i; k < BATCH * HID; k += stride) {
        g_h[0][k] = eh[k];
        g_c[k]    = ec[k];
    }
    if (i < BATCH) {
        g_key[0][i] = 0xFFFFFFFFull;  // idx = 0 (SOS)
        g_key[1][i] = 0ull;
    }
}

// ============================================================
// 128x128 mainloop, 512 threads, BK=16, warp-row mapping:
//   warp w (0..15): rows w*8..w*8+7 (A = smem broadcast)
//   lane l: cols l*4..l*4+3 (B = one LDS128)
// acc[m][p] : f32x2 at (row w*8+m, cols l*4+2p..+1)
// One __syncthreads per K-tile (register double-buffer across smem bufs).
// ============================================================
struct __align__(16) MLSmem {
    float As[2][16][128];
    float Bs[2][16][128];
};

__device__ __forceinline__ void mainloop128(
    const float* __restrict__ aPtr, const float* __restrict__ bPtr,
    MLSmem& s, unsigned long long acc[8][2], int w, int lane, int rl, int kq)
{
    float4 aR = *(const float4*)(aPtr);
    float4 bR = *(const float4*)(bPtr);
    // store tile 0
    s.As[0][kq + 0][rl] = aR.x;  s.As[0][kq + 1][rl] = aR.y;
    s.As[0][kq + 2][rl] = aR.z;  s.As[0][kq + 3][rl] = aR.w;
    s.Bs[0][kq + 0][rl] = bR.x;  s.Bs[0][kq + 1][rl] = bR.y;
    s.Bs[0][kq + 2][rl] = bR.z;  s.Bs[0][kq + 3][rl] = bR.w;

    #pragma unroll 1
    for (int tt = 0; tt < HID / 16; tt++) {
        __syncthreads();
        int buf = tt & 1;
        if (tt + 1 < HID / 16) {
            int k0 = (tt + 1) * 16;
            aR = *(const float4*)(aPtr + k0);
            bR = *(const float4*)(bPtr + k0);
        }
        #pragma unroll
        for (int kk = 0; kk < 16; kk++) {
            float4 a0 = *(const float4*)&s.As[buf][kk][w * 8];
            float4 a1 = *(const float4*)&s.As[buf][kk][w * 8 + 4];
            union { float4 f; unsigned long long u[2]; } bb;
            bb.f = *(const float4*)&s.Bs[buf][kk][lane * 4];
            unsigned long long A0 = pack2(a0.x, a0.x), A1 = pack2(a0.y, a0.y);
            unsigned long long A2 = pack2(a0.z, a0.z), A3 = pack2(a0.w, a0.w);
            unsigned long long A4 = pack2(a1.x, a1.x), A5 = pack2(a1.y, a1.y);
            unsigned long long A6 = pack2(a1.z, a1.z), A7 = pack2(a1.w, a1.w);
            fma2(acc[0][0], A0, bb.u[0]);  fma2(acc[0][1], A0, bb.u[1]);
            fma2(acc[1][0], A1, bb.u[0]);  fma2(acc[1][1], A1, bb.u[1]);
            fma2(acc[2][0], A2, bb.u[0]);  fma2(acc[2][1], A2, bb.u[1]);
            fma2(acc[3][0], A3, bb.u[0]);  fma2(acc[3][1], A3, bb.u[1]);
            fma2(acc[4][0], A4, bb.u[0]);  fma2(acc[4][1], A4, bb.u[1]);
            fma2(acc[5][0], A5, bb.u[0]);  fma2(acc[5][1], A5, bb.u[1]);
            fma2(acc[6][0], A6, bb.u[0]);  fma2(acc[6][1], A6, bb.u[1]);
            fma2(acc[7][0], A7, bb.u[0]);  fma2(acc[7][1], A7, bb.u[1]);
        }
        if (tt + 1 < HID / 16) {
            int nb = buf ^ 1;
            s.As[nb][kq + 0][rl] = aR.x;  s.As[nb][kq + 1][rl] = aR.y;
            s.As[nb][kq + 2][rl] = aR.z;  s.As[nb][kq + 3][rl] = aR.w;
            s.Bs[nb][kq + 0][rl] = bR.x;  s.Bs[nb][kq + 1][rl] = bR.y;
            s.Bs[nb][kq + 2][rl] = bR.z;  s.Bs[nb][kq + 3][rl] = bR.w;
        }
    }
    __syncthreads();   // protect smem reuse after mainloop
}

// ============================================================
// E_proj: E_proj[v][g*H+j] = emb[v]·W_ih[g*H+j] + b_ih + b_hh
// grid (16 j-tiles, 4 v-tiles), 512 threads
// ============================================================
__global__ void __launch_bounds__(512, 1) eproj_kernel(
    const float* __restrict__ emb, const float* __restrict__ Wih,
    const float* __restrict__ b_ih, const float* __restrict__ b_hh)
{
    __shared__ MLSmem s;
    int tid = threadIdx.x, bx = blockIdx.x, by = blockIdx.y;
    int w = tid >> 5, lane = tid & 31;
    int rl = tid & 127, kq = (tid >> 7) * 4;

    unsigned long long acc[8][2];
    #pragma unroll
    for (int m = 0; m < 8; m++) { acc[m][0] = 0ULL; acc[m][1] = 0ULL; }

    int bg = rl >> 5, bj = rl & 31;
    const float* aPtr = emb + (size_t)(by * 128 + rl) * HID + kq;
    const float* bPtr = Wih + (size_t)(bg * HID + bx * 32 + bj) * HID + kq;
    mainloop128(aPtr, bPtr, s, acc, w, lane, rl, kq);

    // cols: c = lane*4 -> gate = lane>>3, strip j = (lane&7)*4
    int gate = lane >> 3;
    int n0 = gate * HID + bx * 32 + (lane & 7) * 4;
    float4 bb = make_float4(b_ih[n0] + b_hh[n0], b_ih[n0+1] + b_hh[n0+1],
                            b_ih[n0+2] + b_hh[n0+2], b_ih[n0+3] + b_hh[n0+3]);
    #pragma unroll
    for (int m = 0; m < 8; m++) {
        int v = by * 128 + w * 8 + m;
        float2 r0 = unpack2(acc[m][0]);
        float2 r1 = unpack2(acc[m][1]);
        *(float4*)&g_EProj[(size_t)v * FH + n0] =
            make_float4(r0.x + bb.x, r0.y + bb.y, r1.x + bb.z, r1.y + bb.w);
    }
}

// ============================================================
// K1: gates = E_proj[idx] + h @ W_hh^T, fused LSTM pointwise
// grid (16 j-tiles, 8 b-tiles), 512 threads
// Epilogue: 2-pass smem re-staging so each thread sees all 4 gates.
// ============================================================
union LstmSmem {
    MLSmem ml;
    float Cs[128][68];   // 34.8KB staging (2 gate strips at a time)
};

__global__ void __launch_bounds__(512, 1) lstm_step_kernel(const float* __restrict__ Whh,
                                                           int parity)
{
    __shared__ LstmSmem u;
    const float* h_in  = g_h[parity];
    float*       h_out = g_h[parity ^ 1];

    int tid = threadIdx.x, bx = blockIdx.x, by = blockIdx.y;
    int w = tid >> 5, lane = tid & 31;
    int rl = tid & 127, kq = (tid >> 7) * 4;

    unsigned long long acc[8][2];
    #pragma unroll
    for (int m = 0; m < 8; m++) { acc[m][0] = 0ULL; acc[m][1] = 0ULL; }

    int bg = rl >> 5, bj = rl & 31;
    const float* aPtr = h_in + (size_t)(by * 128 + rl) * HID + kq;
    const float* bPtr = Whh  + (size_t)(bg * HID + bx * 32 + bj) * HID + kq;
    mainloop128(aPtr, bPtr, u.ml, acc, w, lane, rl, kq);

    // ---------- epilogue ----------
    // pass 1: lanes 0..15 hold gates 0 (i) and 1 (f): cols 0..63
    if (lane < 16) {
        #pragma unroll
        for (int m = 0; m < 8; m++) {
            float2 r0 = unpack2(acc[m][0]);
            float2 r1 = unpack2(acc[m][1]);
            *(float4*)&u.Cs[w * 8 + m][lane * 4] = make_float4(r0.x, r0.y, r1.x, r1.y);
        }
    }
    __syncthreads();

    int r = tid >> 2, q = tid & 3;           // row 0..127, j-octet 0..3
    float4 iv0 = *(const float4*)&u.Cs[r][q * 8];
    float4 iv1 = *(const float4*)&u.Cs[r][q * 8 + 4];
    float4 fv0 = *(const float4*)&u.Cs[r][32 + q * 8];
    float4 fv1 = *(const float4*)&u.Cs[r][32 + q * 8 + 4];
    __syncthreads();

    // pass 2: lanes 16..31 hold gates 2 (g) and 3 (o)
    if (lane >= 16) {
        #pragma unroll
        for (int m = 0; m < 8; m++) {
            float2 r0 = unpack2(acc[m][0]);
            float2 r1 = unpack2(acc[m][1]);
            *(float4*)&u.Cs[w * 8 + m][(lane - 16) * 4] = make_float4(r0.x, r0.y, r1.x, r1.y);
        }
    }
    __syncthreads();

    float4 gv0 = *(const float4*)&u.Cs[r][q * 8];
    float4 gv1 = *(const float4*)&u.Cs[r][q * 8 + 4];
    float4 ov0 = *(const float4*)&u.Cs[r][32 + q * 8];
    float4 ov1 = *(const float4*)&u.Cs[r][32 + q * 8 + 4];

    int b = by * 128 + r;
    unsigned int row = 0xFFFFFFFFu - (unsigned int)(g_key[parity][b]);
    const float* ep = g_EProj + (size_t)row * FH + bx * 32 + q * 8;
    float4 ei0 = *(const float4*)(ep);          float4 ei1 = *(const float4*)(ep + 4);
    float4 ef0 = *(const float4*)(ep + 512);    float4 ef1 = *(const float4*)(ep + 516);
    float4 eg0 = *(const float4*)(ep + 1024);   float4 eg1 = *(const float4*)(ep + 1028);
    float4 eo0 = *(const float4*)(ep + 1536);   float4 eo1 = *(const float4*)(ep + 1540);

    float* cP = &g_c[(size_t)b * HID + bx * 32 + q * 8];
    float* hP = &h_out[(size_t)b * HID + bx * 32 + q * 8];
    float4 c0 = *(const float4*)(cP);
    float4 c1 = *(const float4*)(cP + 4);

    float iarr[8] = {iv0.x+ei0.x, iv0.y+ei0.y, iv0.z+ei0.z, iv0.w+ei0.w,
                     iv1.x+ei1.x, iv1.y+ei1.y, iv1.z+ei1.z, iv1.w+ei1.w};
    float farr[8] = {fv0.x+ef0.x, fv0.y+ef0.y, fv0.z+ef0.z, fv0.w+ef0.w,
                     fv1.x+ef1.x, fv1.y+ef1.y, fv1.z+ef1.z, fv1.w+ef1.w};
    float garr[8] = {gv0.x+eg0.x, gv0.y+eg0.y, gv0.z+eg0.z, gv0.w+eg0.w,
                     gv1.x+eg1.x, gv1.y+eg1.y, gv1.z+eg1.z, gv1.w+eg1.w};
    float oarr[8] = {ov0.x+eo0.x, ov0.y+eo0.y, ov0.z+eo0.z, ov0.w+eo0.w,
                     ov1.x+eo1.x, ov1.y+eo1.y, ov1.z+eo1.z, ov1.w+eo1.w};
    float carr[8] = {c0.x, c0.y, c0.z, c0.w, c1.x, c1.y, c1.z, c1.w};
    float cn[8], hn[8];
    #pragma unroll
    for (int e = 0; e < 8; e++) {
        float i_ = sigf(iarr[e]), f_ = sigf(farr[e]);
        float gv = tanhf(garr[e]), o_ = sigf(oarr[e]);
        cn[e] = f_ * carr[e] + i_ * gv;
        hn[e] = o_ * tanhf(cn[e]);
    }
    *(float4*)(cP)     = make_float4(cn[0], cn[1], cn[2], cn[3]);
    *(float4*)(cP + 4) = make_float4(cn[4], cn[5], cn[6], cn[7]);
    *(float4*)(hP)     = make_float4(hn[0], hn[1], hn[2], hn[3]);
    *(float4*)(hP + 4) = make_float4(hn[4], hn[5], hn[6], hn[7]);
}

// ============================================================
// K2: logits = h_new @ W_out^T + b_out; store; fused argmax
// 64x64 tiles, grid (8 v-tiles, 16 b-tiles) = 128 CTAs, 512 threads.
// In-CTA split-K: warps 0-7 do K[0:256), warps 8-15 do K[256:512).
// ============================================================
union LogSmem {
    struct { float As[2][32][64]; float Bs[2][32][64]; } ml;  // 32KB
    float Cs[64][66];                                         // 16.9KB
};

__global__ void __launch_bounds__(512, 1) logits_kernel(
    const float* __restrict__ Wout, const float* __restrict__ bo,
    float* __restrict__ out_t, int parity, int wb, int zb)
{
    __shared__ LogSmem u;
    const float* h = g_h[parity];
    int tid = threadIdx.x, bx = blockIdx.x, by = blockIdx.y;

    // retire old key buffer (readers finished in prior lstm kernel)
    if (by == 0 && tid < 128) g_key[zb][bx * 128 + tid] = 0ull;

    int w = tid >> 5, lane = tid & 31;
    int half = w >> 3, wr = w & 7;
    int rl = tid & 63, kq = (tid >> 6) * 4;   // load map: 64 rows x 32 k per tile

    unsigned long long acc[8];
    #pragma unroll
    for (int m = 0; m < 8; m++) acc[m] = 0ULL;

    const float* aPtr = h    + (size_t)(by * 64 + rl) * HID + kq;
    const float* bPtr = Wout + (size_t)(bx * 64 + rl) * HID + kq;

    float4 aR = *(const float4*)(aPtr);
    float4 bR = *(const float4*)(bPtr);
    u.ml.As[0][kq + 0][rl] = aR.x;  u.ml.As[0][kq + 1][rl] = aR.y;
    u.ml.As[0][kq + 2][rl] = aR.z;  u.ml.As[0][kq + 3][rl] = aR.w;
    u.ml.Bs[0][kq + 0][rl] = bR.x;  u.ml.Bs[0][kq + 1][rl] = bR.y;
    u.ml.Bs[0][kq + 2][rl] = bR.z;  u.ml.Bs[0][kq + 3][rl] = bR.w;

    #pragma unroll 1
    for (int tt = 0; tt < HID / 32; tt++) {
        __syncthreads();
        int buf = tt & 1;
        if (tt + 1 < HID / 32) {
            int k0 = (tt + 1) * 32;
            aR = *(const float4*)(aPtr + k0);
            bR = *(const float4*)(bPtr + k0);
        }
        #pragma unroll
        for (int kk = 0; kk < 16; kk++) {
            int kh = half * 16 + kk;
            float4 a0 = *(const float4*)&u.ml.As[buf][kh][wr * 8];
            float4 a1 = *(const float4*)&u.ml.As[buf][kh][wr * 8 + 4];
            unsigned long long bv = *(const unsigned long long*)&u.ml.Bs[buf][kh][lane * 2];
            fma2(acc[0], pack2(a0.x, a0.x), bv);
            fma2(acc[1], pack2(a0.y, a0.y), bv);
            fma2(acc[2], pack2(a0.z, a0.z), bv);
            fma2(acc[3], pack2(a0.w, a0.w), bv);
            fma2(acc[4], pack2(a1.x, a1.x), bv);
            fma2(acc[5], pack2(a1.y, a1.y), bv);
            fma2(acc[6], pack2(a1.z, a1.z), bv);
            fma2(acc[7], pack2(a1.w, a1.w), bv);
        }
        if (tt + 1 < HID / 32) {
            int nb = buf ^ 1;
            u.ml.As[nb][kq + 0][rl] = aR.x;  u.ml.As[nb][kq + 1][rl] = aR.y;
            u.ml.As[nb][kq + 2][rl] = aR.z;  u.ml.As[nb][kq + 3][rl] = aR.w;
            u.ml.Bs[nb][kq + 0][rl] = bR.x;  u.ml.Bs[nb][kq + 1][rl] = bR.y;
            u.ml.Bs[nb][kq + 2][rl] = bR.z;  u.ml.Bs[nb][kq + 3][rl] = bR.w;
        }
    }
    __syncthreads();

    // combine halves: upper half stages partials, lower half finishes
    if (half == 1) {
        #pragma unroll
        for (int m = 0; m < 8; m++)
            *(float2*)&u.Cs[wr * 8 + m][lane * 2] = unpack2(acc[m]);
    }
    __syncthreads();

    if (half == 0) {
        int v0 = bx * 64 + lane * 2;
        float2 bb = *(const float2*)&bo[v0];
        #pragma unroll
        for (int m = 0; m < 8; m++) {
            int rloc = wr * 8 + m;
            int b = by * 64 + rloc;
            float2 p  = *(const float2*)&u.Cs[rloc][lane * 2];
            float2 me = unpack2(acc[m]);
            float x0 = me.x + p.x + bb.x;
            float x1 = me.y + p.y + bb.y;
            *(float2*)&out_t[(size_t)b * VOC + v0] = make_float2(x0, x1);

            unsigned long long key = mkkey(x0, v0);
            unsigned long long k1  = mkkey(x1, v0 + 1);
            if (k1 > key) key = k1;
            #pragma unroll
            for (int off = 16; off > 0; off >>= 1) {
                unsigned long long o = __shfl_xor_sync(0xFFFFFFFFu, key, off);
                if (o > key) key = o;
            }
            if (lane == 0) atomicMax(&g_key[wb][b], key);
        }
    }
}

// ============================================================
// launch
// ============================================================
extern "C" void kernel_launch(void* const* d_in, const int* in_sizes, int n_in,
                              void* d_out, int out_size)
{
    int i = 0;
    while (i < n_in && in_sizes[i] != BATCH * HID) i++;
    const float* enc_h = (const float*)d_in[i];
    const float* enc_c = (const float*)d_in[i + 1];
    const float* emb   = (const float*)d_in[i + 2];
    const float* W_ih  = (const float*)d_in[i + 3];
    const float* W_hh  = (const float*)d_in[i + 4];
    const float* b_ih  = (const float*)d_in[i + 5];
    const float* b_hh  = (const float*)d_in[i + 6];
    const float* W_out = (const float*)d_in[i + 7];
    const float* b_out = (const float*)d_in[i + 8];
    float* out = (float*)d_out;

    init_kernel<<<512, 256>>>(enc_h, enc_c);
    eproj_kernel<<<dim3(16, 4), 512>>>(emb, W_ih, b_ih, b_hh);
    for (int t = 0; t < TSTEPS; t++) {
        lstm_step_kernel<<<dim3(16, 8), 512>>>(W_hh, t & 1);
        logits_kernel<<<dim3(8, 16), 512>>>(W_out, b_out,
                                            out + (size_t)t * BATCH * VOC,
                                            (t & 1) ^ 1,   // h parity to read
                                            (t + 1) & 1,   // key buffer to write
                                            t & 1);        // key buffer to retire
    }
}

// round 4
// speedup vs baseline: 1.0024x; 1.0024x over previous
#include <cuda_runtime.h>
#include <math.h>

#define BATCH 1024
#define HID   512
#define VOC   512
#define TSTEPS 64
#define FH    2048   // 4*HID

// -------- persistent device scratch (no allocs allowed) --------
__device__ float g_EProj[VOC * FH];            // embedding @ W_ih^T + bias, 4MB
__device__ float g_h[2][BATCH * HID];          // double-buffered hidden state
__device__ float g_c[BATCH * HID];             // cell state
__device__ unsigned long long g_key[2][BATCH]; // packed (value|~idx) argmax keys

// -------- packed fp32x2 helpers (sm_103a FFMA2 path) --------
__device__ __forceinline__ unsigned long long pack2(float x, float y) {
    unsigned long long r;
    asm("mov.b64 %0, {%1, %2};" : "=l"(r) : "f"(x), "f"(y));
    return r;
}
__device__ __forceinline__ float2 unpack2(unsigned long long v) {
    float2 r;
    asm("mov.b64 {%0, %1}, %2;" : "=f"(r.x), "=f"(r.y) : "l"(v));
    return r;
}
__device__ __forceinline__ void fma2(unsigned long long& d, unsigned long long a,
                                     unsigned long long b) {
    asm("fma.rn.f32x2 %0, %1, %2, %3;" : "=l"(d) : "l"(a), "l"(b), "l"(d));
}
__device__ __forceinline__ float sigf(float x) { return 0.5f * tanhf(0.5f * x) + 0.5f; }

__device__ __forceinline__ unsigned int fmono(float v) {
    unsigned int u = __float_as_uint(v);
    return u ^ ((unsigned int)((int)u >> 31) | 0x80000000u);
}
__device__ __forceinline__ unsigned long long mkkey(float v, int idx) {
    return ((unsigned long long)fmono(v) << 32) | (0xFFFFFFFFu - (unsigned)idx);
}

// ============================================================
// init
// ============================================================
__global__ void __launch_bounds__(256) init_kernel(const float* __restrict__ eh,
                                                   const float* __restrict__ ec) {
    int i = blockIdx.x * blockDim.x + threadIdx.x;
    int stride = gridDim.x * blockDim.x;
    for (int k = i; k < BATCH * HID; k += stride) {
        g_h[0][k] = eh[k];
        g_c[k]    = ec[k];
    }
    if (i < BATCH) {
        g_key[0][i] = 0xFFFFFFFFull;  // idx = 0 (SOS)
        g_key[1][i] = 0ull;
    }
}

// ============================================================
// 128x128 mainloop, 512 threads, BK=16, warp-row mapping:
//   warp w (0..15): rows w*8..w*8+7 (A = smem broadcast)
//   lane l: cols l*4..l*4+3 (B = one LDS128)
// acc[m][p] : f32x2 at (row w*8+m, cols l*4+2p..+1)
// One __syncthreads per K-tile (register double-buffer across smem bufs).
// ============================================================
struct __align__(16) MLSmem {
    float As[2][16][128];
    float Bs[2][16][128];
};

__device__ __forceinline__ void mainloop128(
    const float* __restrict__ aPtr, const float* __restrict__ bPtr,
    MLSmem& s, unsigned long long acc[8][2], int w, int lane, int rl, int kq)
{
    float4 aR = *(const float4*)(aPtr);
    float4 bR = *(const float4*)(bPtr);
    // store tile 0
    s.As[0][kq + 0][rl] = aR.x;  s.As[0][kq + 1][rl] = aR.y;
    s.As[0][kq + 2][rl] = aR.z;  s.As[0][kq + 3][rl] = aR.w;
    s.Bs[0][kq + 0][rl] = bR.x;  s.Bs[0][kq + 1][rl] = bR.y;
    s.Bs[0][kq + 2][rl] = bR.z;  s.Bs[0][kq + 3][rl] = bR.w;

    #pragma unroll 1
    for (int tt = 0; tt < HID / 16; tt++) {
        __syncthreads();
        int buf = tt & 1;
        if (tt + 1 < HID / 16) {
            int k0 = (tt + 1) * 16;
            aR = *(const float4*)(aPtr + k0);
            bR = *(const float4*)(bPtr + k0);
        }
        #pragma unroll
        for (int kk = 0; kk < 16; kk++) {
            float4 a0 = *(const float4*)&s.As[buf][kk][w * 8];
            float4 a1 = *(const float4*)&s.As[buf][kk][w * 8 + 4];
            union { float4 f; unsigned long long u[2]; } bb;
            bb.f = *(const float4*)&s.Bs[buf][kk][lane * 4];
            unsigned long long A0 = pack2(a0.x, a0.x), A1 = pack2(a0.y, a0.y);
            unsigned long long A2 = pack2(a0.z, a0.z), A3 = pack2(a0.w, a0.w);
            unsigned long long A4 = pack2(a1.x, a1.x), A5 = pack2(a1.y, a1.y);
            unsigned long long A6 = pack2(a1.z, a1.z), A7 = pack2(a1.w, a1.w);
            fma2(acc[0][0], A0, bb.u[0]);  fma2(acc[0][1], A0, bb.u[1]);
            fma2(acc[1][0], A1, bb.u[0]);  fma2(acc[1][1], A1, bb.u[1]);
            fma2(acc[2][0], A2, bb.u[0]);  fma2(acc[2][1], A2, bb.u[1]);
            fma2(acc[3][0], A3, bb.u[0]);  fma2(acc[3][1], A3, bb.u[1]);
            fma2(acc[4][0], A4, bb.u[0]);  fma2(acc[4][1], A4, bb.u[1]);
            fma2(acc[5][0], A5, bb.u[0]);  fma2(acc[5][1], A5, bb.u[1]);
            fma2(acc[6][0], A6, bb.u[0]);  fma2(acc[6][1], A6, bb.u[1]);
            fma2(acc[7][0], A7, bb.u[0]);  fma2(acc[7][1], A7, bb.u[1]);
        }
        if (tt + 1 < HID / 16) {
            int nb = buf ^ 1;
            s.As[nb][kq + 0][rl] = aR.x;  s.As[nb][kq + 1][rl] = aR.y;
            s.As[nb][kq + 2][rl] = aR.z;  s.As[nb][kq + 3][rl] = aR.w;
            s.Bs[nb][kq + 0][rl] = bR.x;  s.Bs[nb][kq + 1][rl] = bR.y;
            s.Bs[nb][kq + 2][rl] = bR.z;  s.Bs[nb][kq + 3][rl] = bR.w;
        }
    }
    __syncthreads();   // protect smem reuse after mainloop
}

// ============================================================
// E_proj: E_proj[v][g*H+j] = emb[v]·W_ih[g*H+j] + b_ih + b_hh
// grid (16 j-tiles, 4 v-tiles), 512 threads
// ============================================================
__global__ void __launch_bounds__(512, 1) eproj_kernel(
    const float* __restrict__ emb, const float* __restrict__ Wih,
    const float* __restrict__ b_ih, const float* __restrict__ b_hh)
{
    __shared__ MLSmem s;
    int tid = threadIdx.x, bx = blockIdx.x, by = blockIdx.y;
    int w = tid >> 5, lane = tid & 31;
    int rl = tid & 127, kq = (tid >> 7) * 4;

    unsigned long long acc[8][2];
    #pragma unroll
    for (int m = 0; m < 8; m++) { acc[m][0] = 0ULL; acc[m][1] = 0ULL; }

    int bg = rl >> 5, bj = rl & 31;
    const float* aPtr = emb + (size_t)(by * 128 + rl) * HID + kq;
    const float* bPtr = Wih + (size_t)(bg * HID + bx * 32 + bj) * HID + kq;
    mainloop128(aPtr, bPtr, s, acc, w, lane, rl, kq);

    // cols: c = lane*4 -> gate = lane>>3, strip j = (lane&7)*4
    int gate = lane >> 3;
    int n0 = gate * HID + bx * 32 + (lane & 7) * 4;
    float4 bb = make_float4(b_ih[n0] + b_hh[n0], b_ih[n0+1] + b_hh[n0+1],
                            b_ih[n0+2] + b_hh[n0+2], b_ih[n0+3] + b_hh[n0+3]);
    #pragma unroll
    for (int m = 0; m < 8; m++) {
        int v = by * 128 + w * 8 + m;
        float2 r0 = unpack2(acc[m][0]);
        float2 r1 = unpack2(acc[m][1]);
        *(float4*)&g_EProj[(size_t)v * FH + n0] =
            make_float4(r0.x + bb.x, r0.y + bb.y, r1.x + bb.z, r1.y + bb.w);
    }
}

// ============================================================
// K1: gates = E_proj[idx] + h @ W_hh^T, fused LSTM pointwise
// grid (16 j-tiles, 8 b-tiles), 512 threads
// Epilogue: 2-pass smem re-staging so each thread sees all 4 gates.
// ============================================================
union LstmSmem {
    MLSmem ml;
    float Cs[128][68];   // 34.8KB staging (2 gate strips at a time)
};

__global__ void __launch_bounds__(512, 1) lstm_step_kernel(const float* __restrict__ Whh,
                                                           int parity)
{
    __shared__ LstmSmem u;
    const float* h_in  = g_h[parity];
    float*       h_out = g_h[parity ^ 1];

    int tid = threadIdx.x, bx = blockIdx.x, by = blockIdx.y;
    int w = tid >> 5, lane = tid & 31;
    int rl = tid & 127, kq = (tid >> 7) * 4;

    unsigned long long acc[8][2];
    #pragma unroll
    for (int m = 0; m < 8; m++) { acc[m][0] = 0ULL; acc[m][1] = 0ULL; }

    int bg = rl >> 5, bj = rl & 31;
    const float* aPtr = h_in + (size_t)(by * 128 + rl) * HID + kq;
    const float* bPtr = Whh  + (size_t)(bg * HID + bx * 32 + bj) * HID + kq;
    mainloop128(aPtr, bPtr, u.ml, acc, w, lane, rl, kq);

    // ---------- epilogue ----------
    // pass 1: lanes 0..15 hold gates 0 (i) and 1 (f): cols 0..63
    if (lane < 16) {
        #pragma unroll
        for (int m = 0; m < 8; m++) {
            float2 r0 = unpack2(acc[m][0]);
            float2 r1 = unpack2(acc[m][1]);
            *(float4*)&u.Cs[w * 8 + m][lane * 4] = make_float4(r0.x, r0.y, r1.x, r1.y);
        }
    }
    __syncthreads();

    int r = tid >> 2, q = tid & 3;           // row 0..127, j-octet 0..3
    float4 iv0 = *(const float4*)&u.Cs[r][q * 8];
    float4 iv1 = *(const float4*)&u.Cs[r][q * 8 + 4];
    float4 fv0 = *(const float4*)&u.Cs[r][32 + q * 8];
    float4 fv1 = *(const float4*)&u.Cs[r][32 + q * 8 + 4];
    __syncthreads();

    // pass 2: lanes 16..31 hold gates 2 (g) and 3 (o)
    if (lane >= 16) {
        #pragma unroll
        for (int m = 0; m < 8; m++) {
            float2 r0 = unpack2(acc[m][0]);
            float2 r1 = unpack2(acc[m][1]);
            *(float4*)&u.Cs[w * 8 + m][(lane - 16) * 4] = make_float4(r0.x, r0.y, r1.x, r1.y);
        }
    }
    __syncthreads();

    float4 gv0 = *(const float4*)&u.Cs[r][q * 8];
    float4 gv1 = *(const float4*)&u.Cs[r][q * 8 + 4];
    float4 ov0 = *(const float4*)&u.Cs[r][32 + q * 8];
    float4 ov1 = *(const float4*)&u.Cs[r][32 + q * 8 + 4];

    int b = by * 128 + r;
    unsigned int row = 0xFFFFFFFFu - (unsigned int)(g_key[parity][b]);
    const float* ep = g_EProj + (size_t)row * FH + bx * 32 + q * 8;
    float4 ei0 = *(const float4*)(ep);          float4 ei1 = *(const float4*)(ep + 4);
    float4 ef0 = *(const float4*)(ep + 512);    float4 ef1 = *(const float4*)(ep + 516);
    float4 eg0 = *(const float4*)(ep + 1024);   float4 eg1 = *(const float4*)(ep + 1028);
    float4 eo0 = *(const float4*)(ep + 1536);   float4 eo1 = *(const float4*)(ep + 1540);

    float* cP = &g_c[(size_t)b * HID + bx * 32 + q * 8];
    float* hP = &h_out[(size_t)b * HID + bx * 32 + q * 8];
    float4 c0 = *(const float4*)(cP);
    float4 c1 = *(const float4*)(cP + 4);

    float iarr[8] = {iv0.x+ei0.x, iv0.y+ei0.y, iv0.z+ei0.z, iv0.w+ei0.w,
                     iv1.x+ei1.x, iv1.y+ei1.y, iv1.z+ei1.z, iv1.w+ei1.w};
    float farr[8] = {fv0.x+ef0.x, fv0.y+ef0.y, fv0.z+ef0.z, fv0.w+ef0.w,
                     fv1.x+ef1.x, fv1.y+ef1.y, fv1.z+ef1.z, fv1.w+ef1.w};
    float garr[8] = {gv0.x+eg0.x, gv0.y+eg0.y, gv0.z+eg0.z, gv0.w+eg0.w,
                     gv1.x+eg1.x, gv1.y+eg1.y, gv1.z+eg1.z, gv1.w+eg1.w};
    float oarr[8] = {ov0.x+eo0.x, ov0.y+eo0.y, ov0.z+eo0.z, ov0.w+eo0.w,
                     ov1.x+eo1.x, ov1.y+eo1.y, ov1.z+eo1.z, ov1.w+eo1.w};
    float carr[8] = {c0.x, c0.y, c0.z, c0.w, c1.x, c1.y, c1.z, c1.w};
    float cn[8], hn[8];
    #pragma unroll
    for (int e = 0; e < 8; e++) {
        float i_ = sigf(iarr[e]), f_ = sigf(farr[e]);
        float gv = tanhf(garr[e]), o_ = sigf(oarr[e]);
        cn[e] = f_ * carr[e] + i_ * gv;
        hn[e] = o_ * tanhf(cn[e]);
    }
    *(float4*)(cP)     = make_float4(cn[0], cn[1], cn[2], cn[3]);
    *(float4*)(cP + 4) = make_float4(cn[4], cn[5], cn[6], cn[7]);
    *(float4*)(hP)     = make_float4(hn[0], hn[1], hn[2], hn[3]);
    *(float4*)(hP + 4) = make_float4(hn[4], hn[5], hn[6], hn[7]);
}

// ============================================================
// K2: logits = h_new @ W_out^T + b_out; store; fused argmax
// 64x64 tiles, grid (8 v-tiles, 16 b-tiles) = 128 CTAs, 512 threads.
// In-CTA split-K: warps 0-7 do K[0:256), warps 8-15 do K[256:512).
// ============================================================
union LogSmem {
    struct { float As[2][32][64]; float Bs[2][32][64]; } ml;  // 32KB
    float Cs[64][66];                                         // 16.9KB
};

__global__ void __launch_bounds__(512, 1) logits_kernel(
    const float* __restrict__ Wout, const float* __restrict__ bo,
    float* __restrict__ out_t, int parity, int wb, int zb)
{
    __shared__ LogSmem u;
    const float* h = g_h[parity];
    int tid = threadIdx.x, bx = blockIdx.x, by = blockIdx.y;

    // retire old key buffer (readers finished in prior lstm kernel)
    if (by == 0 && tid < 128) g_key[zb][bx * 128 + tid] = 0ull;

    int w = tid >> 5, lane = tid & 31;
    int half = w >> 3, wr = w & 7;
    int rl = tid & 63, kq = (tid >> 6) * 4;   // load map: 64 rows x 32 k per tile

    unsigned long long acc[8];
    #pragma unroll
    for (int m = 0; m < 8; m++) acc[m] = 0ULL;

    const float* aPtr = h    + (size_t)(by * 64 + rl) * HID + kq;
    const float* bPtr = Wout + (size_t)(bx * 64 + rl) * HID + kq;

    float4 aR = *(const float4*)(aPtr);
    float4 bR = *(const float4*)(bPtr);
    u.ml.As[0][kq + 0][rl] = aR.x;  u.ml.As[0][kq + 1][rl] = aR.y;
    u.ml.As[0][kq + 2][rl] = aR.z;  u.ml.As[0][kq + 3][rl] = aR.w;
    u.ml.Bs[0][kq + 0][rl] = bR.x;  u.ml.Bs[0][kq + 1][rl] = bR.y;
    u.ml.Bs[0][kq + 2][rl] = bR.z;  u.ml.Bs[0][kq + 3][rl] = bR.w;

    #pragma unroll 1
    for (int tt = 0; tt < HID / 32; tt++) {
        __syncthreads();
        int buf = tt & 1;
        if (tt + 1 < HID / 32) {
            int k0 = (tt + 1) * 32;
            aR = *(const float4*)(aPtr + k0);
            bR = *(const float4*)(bPtr + k0);
        }
        #pragma unroll
        for (int kk = 0; kk < 16; kk++) {
            int kh = half * 16 + kk;
            float4 a0 = *(const float4*)&u.ml.As[buf][kh][wr * 8];
            float4 a1 = *(const float4*)&u.ml.As[buf][kh][wr * 8 + 4];
            unsigned long long bv = *(const unsigned long long*)&u.ml.Bs[buf][kh][lane * 2];
            fma2(acc[0], pack2(a0.x, a0.x), bv);
            fma2(acc[1], pack2(a0.y, a0.y), bv);
            fma2(acc[2], pack2(a0.z, a0.z), bv);
            fma2(acc[3], pack2(a0.w, a0.w), bv);
            fma2(acc[4], pack2(a1.x, a1.x), bv);
            fma2(acc[5], pack2(a1.y, a1.y), bv);
            fma2(acc[6], pack2(a1.z, a1.z), bv);
            fma2(acc[7], pack2(a1.w, a1.w), bv);
        }
        if (tt + 1 < HID / 32) {
            int nb = buf ^ 1;
            u.ml.As[nb][kq + 0][rl] = aR.x;  u.ml.As[nb][kq + 1][rl] = aR.y;
            u.ml.As[nb][kq + 2][rl] = aR.z;  u.ml.As[nb][kq + 3][rl] = aR.w;
            u.ml.Bs[nb][kq + 0][rl] = bR.x;  u.ml.Bs[nb][kq + 1][rl] = bR.y;
            u.ml.Bs[nb][kq + 2][rl] = bR.z;  u.ml.Bs[nb][kq + 3][rl] = bR.w;
        }
    }
    __syncthreads();

    // combine halves: upper half stages partials, lower half finishes
    if (half == 1) {
        #pragma unroll
        for (int m = 0; m < 8; m++)
            *(float2*)&u.Cs[wr * 8 + m][lane * 2] = unpack2(acc[m]);
    }
    __syncthreads();

    if (half == 0) {
        int v0 = bx * 64 + lane * 2;
        float2 bb = *(const float2*)&bo[v0];
        #pragma unroll
        for (int m = 0; m < 8; m++) {
            int rloc = wr * 8 + m;
            int b = by * 64 + rloc;
            float2 p  = *(const float2*)&u.Cs[rloc][lane * 2];
            float2 me = unpack2(acc[m]);
            float x0 = me.x + p.x + bb.x;
            float x1 = me.y + p.y + bb.y;
            *(float2*)&out_t[(size_t)b * VOC + v0] = make_float2(x0, x1);

            unsigned long long key = mkkey(x0, v0);
            unsigned long long k1  = mkkey(x1, v0 + 1);
            if (k1 > key) key = k1;
            #pragma unroll
            for (int off = 16; off > 0; off >>= 1) {
                unsigned long long o = __shfl_xor_sync(0xFFFFFFFFu, key, off);
                if (o > key) key = o;
            }
            if (lane == 0) atomicMax(&g_key[wb][b], key);
        }
    }
}

// ============================================================
// launch
// ============================================================
extern "C" void kernel_launch(void* const* d_in, const int* in_sizes, int n_in,
                              void* d_out, int out_size)
{
    int i = 0;
    while (i < n_in && in_sizes[i] != BATCH * HID) i++;
    const float* enc_h = (const float*)d_in[i];
    const float* enc_c = (const float*)d_in[i + 1];
    const float* emb   = (const float*)d_in[i + 2];
    const float* W_ih  = (const float*)d_in[i + 3];
    const float* W_hh  = (const float*)d_in[i + 4];
    const float* b_ih  = (const float*)d_in[i + 5];
    const float* b_hh  = (const float*)d_in[i + 6];
    const float* W_out = (const float*)d_in[i + 7];
    const float* b_out = (const float*)d_in[i + 8];
    float* out = (float*)d_out;

    init_kernel<<<512, 256>>>(enc_h, enc_c);
    eproj_kernel<<<dim3(16, 4), 512>>>(emb, W_ih, b_ih, b_hh);
    for (int t = 0; t < TSTEPS; t++) {
        lstm_step_kernel<<<dim3(16, 8), 512>>>(W_hh, t & 1);
        logits_kernel<<<dim3(8, 16), 512>>>(W_out, b_out,
                                            out + (size_t)t * BATCH * VOC,
                                            (t & 1) ^ 1,   // h parity to read
                                            (t + 1) & 1,   // key buffer to write
                                            t & 1);        // key buffer to retire
    }
}

// round 6
// speedup vs baseline: 1.0398x; 1.0374x over previous
#include <cuda_runtime.h>
#include <math.h>

#define BATCH 1024
#define HID   512
#define VOC   512
#define TSTEPS 64
#define FH    2048   // 4*HID

// -------- persistent device scratch (no allocs allowed) --------
__device__ float g_EProj[VOC * FH];            // embedding @ W_ih^T + bias, 4MB
__device__ float g_h[2][BATCH * HID];          // double-buffered hidden state
__device__ float g_c[BATCH * HID];             // cell state
__device__ unsigned long long g_key[2][BATCH]; // packed (value|~idx) argmax keys

// -------- packed fp32x2 helpers (sm_103a FFMA2 path) --------
__device__ __forceinline__ unsigned long long pack2(float x, float y) {
    unsigned long long r;
    asm("mov.b64 %0, {%1, %2};" : "=l"(r) : "f"(x), "f"(y));
    return r;
}
__device__ __forceinline__ float2 unpack2(unsigned long long v) {
    float2 r;
    asm("mov.b64 {%0, %1}, %2;" : "=f"(r.x), "=f"(r.y) : "l"(v));
    return r;
}
__device__ __forceinline__ void fma2(unsigned long long& d, unsigned long long a,
                                     unsigned long long b) {
    asm("fma.rn.f32x2 %0, %1, %2, %3;" : "=l"(d) : "l"(a), "l"(b), "l"(d));
}
__device__ __forceinline__ float sigf(float x) { return 0.5f * tanhf(0.5f * x) + 0.5f; }

__device__ __forceinline__ unsigned int fmono(float v) {
    unsigned int u = __float_as_uint(v);
    return u ^ ((unsigned int)((int)u >> 31) | 0x80000000u);
}
__device__ __forceinline__ unsigned long long mkkey(float v, int idx) {
    return ((unsigned long long)fmono(v) << 32) | (0xFFFFFFFFu - (unsigned)idx);
}

// ============================================================
// init
// ============================================================
__global__ void __launch_bounds__(256) init_kernel(const float* __restrict__ eh,
                                                   const float* __restrict__ ec) {
    int i = blockIdx.x * blockDim.x + threadIdx.x;
    int stride = gridDim.x * blockDim.x;
    for (int k = i; k < BATCH * HID; k += stride) {
        g_h[0][k] = eh[k];
        g_c[k]    = ec[k];
    }
    if (i < BATCH) {
        g_key[0][i] = 0xFFFFFFFFull;  // idx = 0 (SOS)
        g_key[1][i] = 0ull;
    }
}

// ============================================================
// 128x128 GEMM mainloop (BK=16), 256 threads, 8x8 micro-tile (R2 proven)
// ============================================================
struct __align__(16) SmemT {
    float As[16][128];
    float Bs[16][128];
};

__device__ __forceinline__ void gemm_mainloop128(
    const float* __restrict__ aPtr, const float* __restrict__ bPtr,
    SmemT& s, unsigned long long acc[4][8], int ty, int tx, int rl, int kh)
{
    float4 aR0 = *(const float4*)(aPtr);
    float4 aR1 = *(const float4*)(aPtr + 4);
    float4 bR0 = *(const float4*)(bPtr);
    float4 bR1 = *(const float4*)(bPtr + 4);

    #pragma unroll 1
    for (int tt = 0; tt < HID / 16; tt++) {
        s.As[kh + 0][rl] = aR0.x;  s.As[kh + 1][rl] = aR0.y;
        s.As[kh + 2][rl] = aR0.z;  s.As[kh + 3][rl] = aR0.w;
        s.As[kh + 4][rl] = aR1.x;  s.As[kh + 5][rl] = aR1.y;
        s.As[kh + 6][rl] = aR1.z;  s.As[kh + 7][rl] = aR1.w;
        s.Bs[kh + 0][rl] = bR0.x;  s.Bs[kh + 1][rl] = bR0.y;
        s.Bs[kh + 2][rl] = bR0.z;  s.Bs[kh + 3][rl] = bR0.w;
        s.Bs[kh + 4][rl] = bR1.x;  s.Bs[kh + 5][rl] = bR1.y;
        s.Bs[kh + 6][rl] = bR1.z;  s.Bs[kh + 7][rl] = bR1.w;
        __syncthreads();

        if (tt + 1 < HID / 16) {
            int k0 = (tt + 1) * 16;
            aR0 = *(const float4*)(aPtr + k0);
            aR1 = *(const float4*)(aPtr + k0 + 4);
            bR0 = *(const float4*)(bPtr + k0);
            bR1 = *(const float4*)(bPtr + k0 + 4);
        }

        #pragma unroll
        for (int kk = 0; kk < 16; kk++) {
            float4 a0 = *(const float4*)&s.As[kk][ty * 8];
            float4 a1 = *(const float4*)&s.As[kk][ty * 8 + 4];
            unsigned long long A0 = pack2(a0.x, a0.x), A1 = pack2(a0.y, a0.y);
            unsigned long long A2 = pack2(a0.z, a0.z), A3 = pack2(a0.w, a0.w);
            unsigned long long A4 = pack2(a1.x, a1.x), A5 = pack2(a1.y, a1.y);
            unsigned long long A6 = pack2(a1.z, a1.z), A7 = pack2(a1.w, a1.w);
            #pragma unroll
            for (int g = 0; g < 4; g++) {
                unsigned long long bv =
                    *(const unsigned long long*)&s.Bs[kk][g * 32 + tx * 2];
                fma2(acc[g][0], A0, bv);  fma2(acc[g][1], A1, bv);
                fma2(acc[g][2], A2, bv);  fma2(acc[g][3], A3, bv);
                fma2(acc[g][4], A4, bv);  fma2(acc[g][5], A5, bv);
                fma2(acc[g][6], A6, bv);  fma2(acc[g][7], A7, bv);
            }
        }
        __syncthreads();
    }
}

// ============================================================
// E_proj precompute (R2 proven)
// ============================================================
__global__ void __launch_bounds__(256) eproj_kernel(
    const float* __restrict__ emb, const float* __restrict__ Wih,
    const float* __restrict__ b_ih, const float* __restrict__ b_hh)
{
    __shared__ SmemT s;
    int tid = threadIdx.x, bx = blockIdx.x, by = blockIdx.y;
    int ty = tid >> 4, tx = tid & 15;
    int rl = tid & 127, kh = (tid >> 7) * 8;
    int bg = rl >> 5, bj = rl & 31;

    unsigned long long acc[4][8];
    #pragma unroll
    for (int g = 0; g < 4; g++)
        #pragma unroll
        for (int m = 0; m < 8; m++) acc[g][m] = 0ULL;

    const float* aPtr = emb + (size_t)(by * 128 + rl) * HID + kh;
    const float* bPtr = Wih + (size_t)(bg * HID + bx * 32 + bj) * HID + kh;
    gemm_mainloop128(aPtr, bPtr, s, acc, ty, tx, rl, kh);

    int jBase = bx * 32 + tx * 2;
    #pragma unroll
    for (int m = 0; m < 8; m++) {
        int v = by * 128 + ty * 8 + m;
        #pragma unroll
        for (int g = 0; g < 4; g++) {
            float2 r = unpack2(acc[g][m]);
            int n0 = g * HID + jBase;
            r.x += b_ih[n0]     + b_hh[n0];
            r.y += b_ih[n0 + 1] + b_hh[n0 + 1];
            *(float2*)&g_EProj[(size_t)v * FH + n0] = r;
        }
    }
}

// ============================================================
// K1: gates = E_proj[idx] + h @ W_hh^T, fused LSTM pointwise (R2 proven)
// grid (16 j-tiles, 8 b-tiles), 256 threads
// ============================================================
__global__ void __launch_bounds__(256) lstm_step_kernel(const float* __restrict__ Whh,
                                                        int parity)
{
    __shared__ SmemT s;
    const float* h_in  = g_h[parity];
    float*       h_out = g_h[parity ^ 1];

    int tid = threadIdx.x, bx = blockIdx.x, by = blockIdx.y;
    int ty = tid >> 4, tx = tid & 15;
    int rl = tid & 127, kh = (tid >> 7) * 8;
    int bg = rl >> 5, bj = rl & 31;

    unsigned long long acc[4][8];
    #pragma unroll
    for (int g = 0; g < 4; g++)
        #pragma unroll
        for (int m = 0; m < 8; m++) acc[g][m] = 0ULL;

    const float* aPtr = h_in + (size_t)(by * 128 + rl) * HID + kh;
    const float* bPtr = Whh  + (size_t)(bg * HID + bx * 32 + bj) * HID + kh;
    gemm_mainloop128(aPtr, bPtr, s, acc, ty, tx, rl, kh);

    int jBase = bx * 32 + tx * 2;
    #pragma unroll
    for (int m = 0; m < 8; m++) {
        int b = by * 128 + ty * 8 + m;
        unsigned int row = 0xFFFFFFFFu - (unsigned int)(g_key[parity][b]);
        const float* ep = g_EProj + (size_t)row * FH + jBase;

        float2 gi = unpack2(acc[0][m]);
        float2 gf = unpack2(acc[1][m]);
        float2 gg = unpack2(acc[2][m]);
        float2 go = unpack2(acc[3][m]);
        float2 e;
        e = *(const float2*)(ep +    0); gi.x += e.x; gi.y += e.y;
        e = *(const float2*)(ep +  512); gf.x += e.x; gf.y += e.y;
        e = *(const float2*)(ep + 1024); gg.x += e.x; gg.y += e.y;
        e = *(const float2*)(ep + 1536); go.x += e.x; go.y += e.y;

        float2 cold = *(const float2*)&g_c[(size_t)b * HID + jBase];
        float2 cn, hn;
        {
            float i_ = sigf(gi.x), f_ = sigf(gf.x), gv = tanhf(gg.x), o_ = sigf(go.x);
            cn.x = f_ * cold.x + i_ * gv;
            hn.x = o_ * tanhf(cn.x);
        }
        {
            float i_ = sigf(gi.y), f_ = sigf(gf.y), gv = tanhf(gg.y), o_ = sigf(go.y);
            cn.y = f_ * cold.y + i_ * gv;
            hn.y = o_ * tanhf(cn.y);
        }
        *(float2*)&g_c[(size_t)b * HID + jBase]   = cn;
        *(float2*)&h_out[(size_t)b * HID + jBase] = hn;
    }
}

// ============================================================
// K2 (new): logits = h @ W_out^T + b_out; store; fused argmax
// 64x64 tiles, grid (8 v-tiles, 16 b-tiles) = 128 CTAs, 512 threads.
// In-CTA split-K = 4: warp-group kg (4 warps) owns K slice [kg*128, kg*128+128).
// Thread micro-tile: 4 rows x 8 cols = 16 fma2/kk from 3 LDS128.
// Combine: tree through smem, group 0 finishes (bias/store/argmax).
// ============================================================
__global__ void __launch_bounds__(512, 1) logits_kernel(
    const float* __restrict__ Wout, const float* __restrict__ bo,
    float* __restrict__ out_t, int parity, int wb, int zb)
{
    __shared__ union {
        struct { float As[2][4][8][64]; float Bs[2][4][8][64]; } m;  // 32KB
        float Cs[2][64][64];                                          // 32KB
    } u;
    const float* h = g_h[parity];
    int tid = threadIdx.x, bx = blockIdx.x, by = blockIdx.y;

    // retire old key buffer (its readers ran in the preceding lstm kernel)
    if (by == 0 && tid < 128) g_key[zb][bx * 128 + tid] = 0ull;

    // loader mapping: row 0..63, g 0..3, kq in {0,4}
    int lrow = tid & 63;
    int gq = tid >> 6;            // 0..7
    int lg = gq >> 1;             // loader k-group
    int kq = (gq & 1) * 4;        // k quad within the 8-k slab

    // compute mapping
    int w = tid >> 5, lane = tid & 31;
    int kg = w >> 2, wr = w & 3;               // k-group, warp-in-group
    int r0 = wr * 16 + (lane >> 3) * 4;        // 4 rows
    int c0 = (lane & 7) * 8;                   // 8 cols

    unsigned long long acc[4][4];
    #pragma unroll
    for (int m = 0; m < 4; m++)
        #pragma unroll
        for (int p = 0; p < 4; p++) acc[m][p] = 0ULL;

    const float* aPtr = h    + (size_t)(by * 64 + lrow) * HID + lg * 128 + kq;
    const float* bPtr = Wout + (size_t)(bx * 64 + lrow) * HID + lg * 128 + kq;

    float4 aR = *(const float4*)(aPtr);
    float4 bR = *(const float4*)(bPtr);
    u.m.As[0][lg][kq + 0][lrow] = aR.x;  u.m.As[0][lg][kq + 1][lrow] = aR.y;
    u.m.As[0][lg][kq + 2][lrow] = aR.z;  u.m.As[0][lg][kq + 3][lrow] = aR.w;
    u.m.Bs[0][lg][kq + 0][lrow] = bR.x;  u.m.Bs[0][lg][kq + 1][lrow] = bR.y;
    u.m.Bs[0][lg][kq + 2][lrow] = bR.z;  u.m.Bs[0][lg][kq + 3][lrow] = bR.w;

    #pragma unroll 1
    for (int tt = 0; tt < 16; tt++) {
        __syncthreads();
        int buf = tt & 1;
        if (tt + 1 < 16) {
            aR = *(const float4*)(aPtr + (tt + 1) * 8);
            bR = *(const float4*)(bPtr + (tt + 1) * 8);
        }
        #pragma unroll
        for (int kk = 0; kk < 8; kk++) {
            float4 av = *(const float4*)&u.m.As[buf][kg][kk][r0];
            union { float4 f; unsigned long long q[2]; } b0, b1;
            b0.f = *(const float4*)&u.m.Bs[buf][kg][kk][c0];
            b1.f = *(const float4*)&u.m.Bs[buf][kg][kk][c0 + 4];
            unsigned long long A0 = pack2(av.x, av.x), A1 = pack2(av.y, av.y);
            unsigned long long A2 = pack2(av.z, av.z), A3 = pack2(av.w, av.w);
            fma2(acc[0][0], A0, b0.q[0]);  fma2(acc[0][1], A0, b0.q[1]);
            fma2(acc[0][2], A0, b1.q[0]);  fma2(acc[0][3], A0, b1.q[1]);
            fma2(acc[1][0], A1, b0.q[0]);  fma2(acc[1][1], A1, b0.q[1]);
            fma2(acc[1][2], A1, b1.q[0]);  fma2(acc[1][3], A1, b1.q[1]);
            fma2(acc[2][0], A2, b0.q[0]);  fma2(acc[2][1], A2, b0.q[1]);
            fma2(acc[2][2], A2, b1.q[0]);  fma2(acc[2][3], A2, b1.q[1]);
            fma2(acc[3][0], A3, b0.q[0]);  fma2(acc[3][1], A3, b0.q[1]);
            fma2(acc[3][2], A3, b1.q[0]);  fma2(acc[3][3], A3, b1.q[1]);
        }
        if (tt + 1 < 16) {
            int nb = buf ^ 1;
            u.m.As[nb][lg][kq + 0][lrow] = aR.x;  u.m.As[nb][lg][kq + 1][lrow] = aR.y;
            u.m.As[nb][lg][kq + 2][lrow] = aR.z;  u.m.As[nb][lg][kq + 3][lrow] = aR.w;
            u.m.Bs[nb][lg][kq + 0][lrow] = bR.x;  u.m.Bs[nb][lg][kq + 1][lrow] = bR.y;
            u.m.Bs[nb][lg][kq + 2][lrow] = bR.z;  u.m.Bs[nb][lg][kq + 3][lrow] = bR.w;
        }
    }
    __syncthreads();   // smem about to be reused as Cs

    // ---- combine stage A: groups 1 & 3 stage partials ----
    if (kg & 1) {
        int half = kg >> 1;
        #pragma unroll
        for (int m = 0; m < 4; m++) {
            float2 p0 = unpack2(acc[m][0]), p1 = unpack2(acc[m][1]);
            float2 p2 = unpack2(acc[m][2]), p3 = unpack2(acc[m][3]);
            *(float4*)&u.Cs[half][r0 + m][c0]     = make_float4(p0.x, p0.y, p1.x, p1.y);
            *(float4*)&u.Cs[half][r0 + m][c0 + 4] = make_float4(p2.x, p2.y, p3.x, p3.y);
        }
    }
    __syncthreads();
    if (!(kg & 1)) {
        int half = kg >> 1;
        #pragma unroll
        for (int m = 0; m < 4; m++) {
            float4 q0 = *(const float4*)&u.Cs[half][r0 + m][c0];
            float4 q1 = *(const float4*)&u.Cs[half][r0 + m][c0 + 4];
            unsigned long long s0 = pack2(q0.x, q0.y), s1 = pack2(q0.z, q0.w);
            unsigned long long s2 = pack2(q1.x, q1.y), s3 = pack2(q1.z, q1.w);
            // acc += staged (fma with 1.0)
            unsigned long long one = pack2(1.0f, 1.0f);
            fma2(acc[m][0], one, s0);  fma2(acc[m][1], one, s1);
            fma2(acc[m][2], one, s2);  fma2(acc[m][3], one, s3);
        }
    }
    __syncthreads();
    // ---- stage B: group 2 stages, group 0 finishes ----
    if (kg == 2) {
        #pragma unroll
        for (int m = 0; m < 4; m++) {
            float2 p0 = unpack2(acc[m][0]), p1 = unpack2(acc[m][1]);
            float2 p2 = unpack2(acc[m][2]), p3 = unpack2(acc[m][3]);
            *(float4*)&u.Cs[0][r0 + m][c0]     = make_float4(p0.x, p0.y, p1.x, p1.y);
            *(float4*)&u.Cs[0][r0 + m][c0 + 4] = make_float4(p2.x, p2.y, p3.x, p3.y);
        }
    }
    __syncthreads();
    if (kg == 0) {
        int v0 = bx * 64 + c0;
        float4 bo0 = *(const float4*)&bo[v0];
        float4 bo1 = *(const float4*)&bo[v0 + 4];
        #pragma unroll
        for (int m = 0; m < 4; m++) {
            int b = by * 64 + r0 + m;
            float4 q0 = *(const float4*)&u.Cs[0][r0 + m][c0];
            float4 q1 = *(const float4*)&u.Cs[0][r0 + m][c0 + 4];
            float2 a0 = unpack2(acc[m][0]), a1 = unpack2(acc[m][1]);
            float2 a2 = unpack2(acc[m][2]), a3 = unpack2(acc[m][3]);
            float x0 = a0.x + q0.x + bo0.x;
            float x1 = a0.y + q0.y + bo0.y;
            float x2 = a1.x + q0.z + bo0.z;
            float x3 = a1.y + q0.w + bo0.w;
            float x4 = a2.x + q1.x + bo1.x;
            float x5 = a2.y + q1.y + bo1.y;
            float x6 = a3.x + q1.z + bo1.z;
            float x7 = a3.y + q1.w + bo1.w;
            float* orow = out_t + (size_t)b * VOC + v0;
            *(float4*)(orow)     = make_float4(x0, x1, x2, x3);
            *(float4*)(orow + 4) = make_float4(x4, x5, x6, x7);

            unsigned long long key = mkkey(x0, v0);
            unsigned long long kk1 = mkkey(x1, v0 + 1);  if (kk1 > key) key = kk1;
            kk1 = mkkey(x2, v0 + 2);  if (kk1 > key) key = kk1;
            kk1 = mkkey(x3, v0 + 3);  if (kk1 > key) key = kk1;
            kk1 = mkkey(x4, v0 + 4);  if (kk1 > key) key = kk1;
            kk1 = mkkey(x5, v0 + 5);  if (kk1 > key) key = kk1;
            kk1 = mkkey(x6, v0 + 6);  if (kk1 > key) key = kk1;
            kk1 = mkkey(x7, v0 + 7);  if (kk1 > key) key = kk1;

            // reduce across the 8 lanes (lane&7) sharing this row
            #pragma unroll
            for (int off = 1; off < 8; off <<= 1) {
                unsigned long long o = __shfl_xor_sync(0xFFFFFFFFu, key, off);
                if (o > key) key = o;
            }
            if ((lane & 7) == 0) atomicMax(&g_key[wb][b], key);
        }
    }
}

// ============================================================
// launch
// ============================================================
extern "C" void kernel_launch(void* const* d_in, const int* in_sizes, int n_in,
                              void* d_out, int out_size)
{
    int i = 0;
    while (i < n_in && in_sizes[i] != BATCH * HID) i++;
    const float* enc_h = (const float*)d_in[i];
    const float* enc_c = (const float*)d_in[i + 1];
    const float* emb   = (const float*)d_in[i + 2];
    const float* W_ih  = (const float*)d_in[i + 3];
    const float* W_hh  = (const float*)d_in[i + 4];
    const float* b_ih  = (const float*)d_in[i + 5];
    const float* b_hh  = (const float*)d_in[i + 6];
    const float* W_out = (const float*)d_in[i + 7];
    const float* b_out = (const float*)d_in[i + 8];
    float* out = (float*)d_out;

    init_kernel<<<512, 256>>>(enc_h, enc_c);
    eproj_kernel<<<dim3(16, 4), 256>>>(emb, W_ih, b_ih, b_hh);
    for (int t = 0; t < TSTEPS; t++) {
        lstm_step_kernel<<<dim3(16, 8), 256>>>(W_hh, t & 1);
        logits_kernel<<<dim3(8, 16), 512>>>(W_out, b_out,
                                            out + (size_t)t * BATCH * VOC,
                                            (t & 1) ^ 1,   // h parity to read
                                            (t + 1) & 1,   // key buffer to write
                                            t & 1);        // key buffer to retire
    }
}

// round 7
// speedup vs baseline: 1.2232x; 1.1763x over previous
#include <cuda_runtime.h>
#include <math.h>

#define BATCH 1024
#define HID   512
#define VOC   512
#define TSTEPS 64
#define FH    2048   // 4*HID

// -------- persistent device scratch (no allocs allowed) --------
__device__ float g_EProj[VOC * FH];            // embedding @ W_ih^T + bias, 4MB
__device__ float g_h[2][BATCH * HID];          // double-buffered hidden state
__device__ float g_c[BATCH * HID];             // cell state
__device__ unsigned long long g_key[2][BATCH]; // packed (value|~idx) argmax keys
__device__ int   g_done[TSTEPS + 1][8];        // per-(step, b-tile) arrival counters

// -------- packed fp32x2 helpers (sm_103a FFMA2 path) --------
__device__ __forceinline__ unsigned long long pack2(float x, float y) {
    unsigned long long r;
    asm("mov.b64 %0, {%1, %2};" : "=l"(r) : "f"(x), "f"(y));
    return r;
}
__device__ __forceinline__ float2 unpack2(unsigned long long v) {
    float2 r;
    asm("mov.b64 {%0, %1}, %2;" : "=f"(r.x), "=f"(r.y) : "l"(v));
    return r;
}
__device__ __forceinline__ void fma2(unsigned long long& d, unsigned long long a,
                                     unsigned long long b) {
    asm("fma.rn.f32x2 %0, %1, %2, %3;" : "=l"(d) : "l"(a), "l"(b), "l"(d));
}
__device__ __forceinline__ float sigf(float x) { return 0.5f * tanhf(0.5f * x) + 0.5f; }

__device__ __forceinline__ unsigned int fmono(float v) {
    unsigned int u = __float_as_uint(v);
    return u ^ ((unsigned int)((int)u >> 31) | 0x80000000u);
}
__device__ __forceinline__ unsigned long long mkkey(float v, int idx) {
    return ((unsigned long long)fmono(v) << 32) | (0xFFFFFFFFu - (unsigned)idx);
}

// ============================================================
// init: h0/c0, zero both key buffers, zero done counters
// ============================================================
__global__ void __launch_bounds__(256) init_kernel(const float* __restrict__ eh,
                                                   const float* __restrict__ ec) {
    int i = blockIdx.x * blockDim.x + threadIdx.x;
    int stride = gridDim.x * blockDim.x;
    for (int k = i; k < BATCH * HID; k += stride) {
        g_h[0][k] = eh[k];
        g_c[k]    = ec[k];
    }
    if (i < BATCH) {
        g_key[0][i] = 0ull;
        g_key[1][i] = 0ull;
    }
    if (i < (TSTEPS + 1) * 8) ((int*)g_done)[i] = 0;
}

// ============================================================
// E_proj precompute (R2 proven): E_proj[v][g*H+j] = emb[v]·W_ih[g*H+j] + biases
// ============================================================
struct __align__(16) SmemT {
    float As[16][128];
    float Bs[16][128];
};

__global__ void __launch_bounds__(256) eproj_kernel(
    const float* __restrict__ emb, const float* __restrict__ Wih,
    const float* __restrict__ b_ih, const float* __restrict__ b_hh)
{
    __shared__ SmemT s;
    int tid = threadIdx.x, bx = blockIdx.x, by = blockIdx.y;
    int ty = tid >> 4, tx = tid & 15;
    int rl = tid & 127, kh = (tid >> 7) * 8;
    int bg = rl >> 5, bj = rl & 31;

    unsigned long long acc[4][8];
    #pragma unroll
    for (int g = 0; g < 4; g++)
        #pragma unroll
        for (int m = 0; m < 8; m++) acc[g][m] = 0ULL;

    const float* aPtr = emb + (size_t)(by * 128 + rl) * HID + kh;
    const float* bPtr = Wih + (size_t)(bg * HID + bx * 32 + bj) * HID + kh;

    float4 aR0 = *(const float4*)(aPtr);
    float4 aR1 = *(const float4*)(aPtr + 4);
    float4 bR0 = *(const float4*)(bPtr);
    float4 bR1 = *(const float4*)(bPtr + 4);

    #pragma unroll 1
    for (int tt = 0; tt < HID / 16; tt++) {
        s.As[kh + 0][rl] = aR0.x;  s.As[kh + 1][rl] = aR0.y;
        s.As[kh + 2][rl] = aR0.z;  s.As[kh + 3][rl] = aR0.w;
        s.As[kh + 4][rl] = aR1.x;  s.As[kh + 5][rl] = aR1.y;
        s.As[kh + 6][rl] = aR1.z;  s.As[kh + 7][rl] = aR1.w;
        s.Bs[kh + 0][rl] = bR0.x;  s.Bs[kh + 1][rl] = bR0.y;
        s.Bs[kh + 2][rl] = bR0.z;  s.Bs[kh + 3][rl] = bR0.w;
        s.Bs[kh + 4][rl] = bR1.x;  s.Bs[kh + 5][rl] = bR1.y;
        s.Bs[kh + 6][rl] = bR1.z;  s.Bs[kh + 7][rl] = bR1.w;
        __syncthreads();

        if (tt + 1 < HID / 16) {
            int k0 = (tt + 1) * 16;
            aR0 = *(const float4*)(aPtr + k0);
            aR1 = *(const float4*)(aPtr + k0 + 4);
            bR0 = *(const float4*)(bPtr + k0);
            bR1 = *(const float4*)(bPtr + k0 + 4);
        }

        #pragma unroll
        for (int kk = 0; kk < 16; kk++) {
            float4 a0 = *(const float4*)&s.As[kk][ty * 8];
            float4 a1 = *(const float4*)&s.As[kk][ty * 8 + 4];
            unsigned long long A0 = pack2(a0.x, a0.x), A1 = pack2(a0.y, a0.y);
            unsigned long long A2 = pack2(a0.z, a0.z), A3 = pack2(a0.w, a0.w);
            unsigned long long A4 = pack2(a1.x, a1.x), A5 = pack2(a1.y, a1.y);
            unsigned long long A6 = pack2(a1.z, a1.z), A7 = pack2(a1.w, a1.w);
            #pragma unroll
            for (int g = 0; g < 4; g++) {
                unsigned long long bv =
                    *(const unsigned long long*)&s.Bs[kk][g * 32 + tx * 2];
                fma2(acc[g][0], A0, bv);  fma2(acc[g][1], A1, bv);
                fma2(acc[g][2], A2, bv);  fma2(acc[g][3], A3, bv);
                fma2(acc[g][4], A4, bv);  fma2(acc[g][5], A5, bv);
                fma2(acc[g][6], A6, bv);  fma2(acc[g][7], A7, bv);
            }
        }
        __syncthreads();
    }

    int jBase = bx * 32 + tx * 2;
    #pragma unroll
    for (int m = 0; m < 8; m++) {
        int v = by * 128 + ty * 8 + m;
        #pragma unroll
        for (int g = 0; g < 4; g++) {
            float2 r = unpack2(acc[g][m]);
            int n0 = g * HID + jBase;
            r.x += b_ih[n0]     + b_hh[n0];
            r.y += b_ih[n0 + 1] + b_hh[n0 + 1];
            *(float2*)&g_EProj[(size_t)v * FH + n0] = r;
        }
    }
}

// ============================================================
// Fused step kernel K_t: from h(t) compute BOTH
//   gates-pre = h(t) @ W_hh^T  (128x128 tile, R2 mainloop)
//   logits(t-1) strip = h(t) @ W_out^T cols [jx*32, jx*32+32)  (reuses A regs)
// then: publish argmax keys, sync the 16 CTAs sharing this b-tile,
// and run the LSTM epilogue with the freshly decoded idx.
// grid (16 jx, 8 by) = 128 CTAs (single wave on 148 SMs), 256 threads.
// ============================================================
__global__ void __launch_bounds__(256, 1) step_kernel(
    const float* __restrict__ Whh, const float* __restrict__ Wout,
    const float* __restrict__ bo, float* __restrict__ out_prev, int t)
{
    __shared__ SmemT s;
    __shared__ __align__(8) float Ws[16][32];

    int tid = threadIdx.x, bx = blockIdx.x, by = blockIdx.y;
    int parity = t & 1;
    const float* h_in  = g_h[parity];
    float*       h_out = g_h[parity ^ 1];

    // zero the key buffer the NEXT step will use (safe: this kernel only
    // touches g_key[parity]; K_{t+1} reads/writes g_key[parity^1] after us)
    if (bx == 0 && tid < 128) g_key[parity ^ 1][by * 128 + tid] = 0ull;

    int ty = tid >> 4, tx = tid & 15;
    int rl = tid & 127, kh = (tid >> 7) * 8;
    int bg = rl >> 5, bj = rl & 31;
    int wrow = tid & 31, wk = (tid >> 5) * 2;   // Wout loader mapping

    unsigned long long acc[4][8];
    unsigned long long accw[8];
    #pragma unroll
    for (int g = 0; g < 4; g++)
        #pragma unroll
        for (int m = 0; m < 8; m++) acc[g][m] = 0ULL;
    #pragma unroll
    for (int m = 0; m < 8; m++) accw[m] = 0ULL;

    const float* aPtr = h_in + (size_t)(by * 128 + rl) * HID + kh;
    const float* bPtr = Whh  + (size_t)(bg * HID + bx * 32 + bj) * HID + kh;
    const float* wPtr = Wout + (size_t)(bx * 32 + wrow) * HID + wk;

    float4 aR0 = *(const float4*)(aPtr);
    float4 aR1 = *(const float4*)(aPtr + 4);
    float4 bR0 = *(const float4*)(bPtr);
    float4 bR1 = *(const float4*)(bPtr + 4);
    float2 wR  = *(const float2*)(wPtr);

    #pragma unroll 1
    for (int tt = 0; tt < HID / 16; tt++) {
        s.As[kh + 0][rl] = aR0.x;  s.As[kh + 1][rl] = aR0.y;
        s.As[kh + 2][rl] = aR0.z;  s.As[kh + 3][rl] = aR0.w;
        s.As[kh + 4][rl] = aR1.x;  s.As[kh + 5][rl] = aR1.y;
        s.As[kh + 6][rl] = aR1.z;  s.As[kh + 7][rl] = aR1.w;
        s.Bs[kh + 0][rl] = bR0.x;  s.Bs[kh + 1][rl] = bR0.y;
        s.Bs[kh + 2][rl] = bR0.z;  s.Bs[kh + 3][rl] = bR0.w;
        s.Bs[kh + 4][rl] = bR1.x;  s.Bs[kh + 5][rl] = bR1.y;
        s.Bs[kh + 6][rl] = bR1.z;  s.Bs[kh + 7][rl] = bR1.w;
        Ws[wk + 0][wrow] = wR.x;
        Ws[wk + 1][wrow] = wR.y;
        __syncthreads();

        if (tt + 1 < HID / 16) {
            int k0 = (tt + 1) * 16;
            aR0 = *(const float4*)(aPtr + k0);
            aR1 = *(const float4*)(aPtr + k0 + 4);
            bR0 = *(const float4*)(bPtr + k0);
            bR1 = *(const float4*)(bPtr + k0 + 4);
            wR  = *(const float2*)(wPtr + k0);
        }

        #pragma unroll
        for (int kk = 0; kk < 16; kk++) {
            float4 a0 = *(const float4*)&s.As[kk][ty * 8];
            float4 a1 = *(const float4*)&s.As[kk][ty * 8 + 4];
            unsigned long long A0 = pack2(a0.x, a0.x), A1 = pack2(a0.y, a0.y);
            unsigned long long A2 = pack2(a0.z, a0.z), A3 = pack2(a0.w, a0.w);
            unsigned long long A4 = pack2(a1.x, a1.x), A5 = pack2(a1.y, a1.y);
            unsigned long long A6 = pack2(a1.z, a1.z), A7 = pack2(a1.w, a1.w);
            #pragma unroll
            for (int g = 0; g < 4; g++) {
                unsigned long long bv =
                    *(const unsigned long long*)&s.Bs[kk][g * 32 + tx * 2];
                fma2(acc[g][0], A0, bv);  fma2(acc[g][1], A1, bv);
                fma2(acc[g][2], A2, bv);  fma2(acc[g][3], A3, bv);
                fma2(acc[g][4], A4, bv);  fma2(acc[g][5], A5, bv);
                fma2(acc[g][6], A6, bv);  fma2(acc[g][7], A7, bv);
            }
            unsigned long long wv =
                *(const unsigned long long*)&Ws[kk][tx * 2];
            fma2(accw[0], A0, wv);  fma2(accw[1], A1, wv);
            fma2(accw[2], A2, wv);  fma2(accw[3], A3, wv);
            fma2(accw[4], A4, wv);  fma2(accw[5], A5, wv);
            fma2(accw[6], A6, wv);  fma2(accw[7], A7, wv);
        }
        __syncthreads();
    }

    // ---------- logits epilogue: bias, store out[t-1], argmax keys ----------
    int colb = bx * 32 + tx * 2;
    float2 bb = *(const float2*)&bo[colb];
    #pragma unroll
    for (int m = 0; m < 8; m++) {
        int b = by * 128 + ty * 8 + m;
        float2 lw = unpack2(accw[m]);
        float x0 = lw.x + bb.x;
        float x1 = lw.y + bb.y;
        *(float2*)&out_prev[(size_t)b * VOC + colb] = make_float2(x0, x1);

        unsigned long long key = mkkey(x0, colb);
        unsigned long long k1  = mkkey(x1, colb + 1);
        if (k1 > key) key = k1;
        // reduce over the 16 lanes (same ty) sharing this row
        #pragma unroll
        for (int off = 8; off > 0; off >>= 1) {
            unsigned long long o = __shfl_down_sync(0xFFFFFFFFu, key, off, 16);
            if (o > key) key = o;
        }
        if (tx == 0) atomicMax(&g_key[parity][b], key);
    }

    // ---------- cross-CTA sync: wait for all 16 jx CTAs of this b-tile ----------
    __threadfence();
    __syncthreads();
    if (tid == 0) {
        atomicAdd(&g_done[t][by], 1);
        volatile int* p = &g_done[t][by];
        while (*p < 16) __nanosleep(64);
    }
    __syncthreads();

    // ---------- LSTM epilogue (R2 proven), idx decoded from fresh keys ----------
    int jBase = bx * 32 + tx * 2;
    #pragma unroll
    for (int m = 0; m < 8; m++) {
        int b = by * 128 + ty * 8 + m;
        unsigned int row;
        if (t == 0) {
            row = 0;  // SOS
        } else {
            unsigned long long kv =
                *(volatile unsigned long long*)&g_key[parity][b];
            row = 0xFFFFFFFFu - (unsigned int)kv;
        }
        const float* ep = g_EProj + (size_t)row * FH + jBase;

        float2 gi = unpack2(acc[0][m]);
        float2 gf = unpack2(acc[1][m]);
        float2 gg = unpack2(acc[2][m]);
        float2 go = unpack2(acc[3][m]);
        float2 e;
        e = *(const float2*)(ep +    0); gi.x += e.x; gi.y += e.y;
        e = *(const float2*)(ep +  512); gf.x += e.x; gf.y += e.y;
        e = *(const float2*)(ep + 1024); gg.x += e.x; gg.y += e.y;
        e = *(const float2*)(ep + 1536); go.x += e.x; go.y += e.y;

        float2 cold = *(const float2*)&g_c[(size_t)b * HID + jBase];
        float2 cn, hn;
        {
            float i_ = sigf(gi.x), f_ = sigf(gf.x), gv = tanhf(gg.x), o_ = sigf(go.x);
            cn.x = f_ * cold.x + i_ * gv;
            hn.x = o_ * tanhf(cn.x);
        }
        {
            float i_ = sigf(gi.y), f_ = sigf(gf.y), gv = tanhf(gg.y), o_ = sigf(go.y);
            cn.y = f_ * cold.y + i_ * gv;
            hn.y = o_ * tanhf(cn.y);
        }
        *(float2*)&g_c[(size_t)b * HID + jBase]   = cn;
        *(float2*)&h_out[(size_t)b * HID + jBase] = hn;
    }
}

// ============================================================
// launch: init, eproj, then 65 fused step kernels
//   K_t computes h(t+1) and logits(t-1) (K_0's logits slot is garbage,
//   overwritten by K_1; K_64 produces the final logits(63)).
// ============================================================
extern "C" void kernel_launch(void* const* d_in, const int* in_sizes, int n_in,
                              void* d_out, int out_size)
{
    int i = 0;
    while (i < n_in && in_sizes[i] != BATCH * HID) i++;
    const float* enc_h = (const float*)d_in[i];
    const float* enc_c = (const float*)d_in[i + 1];
    const float* emb   = (const float*)d_in[i + 2];
    const float* W_ih  = (const float*)d_in[i + 3];
    const float* W_hh  = (const float*)d_in[i + 4];
    const float* b_ih  = (const float*)d_in[i + 5];
    const float* b_hh  = (const float*)d_in[i + 6];
    const float* W_out = (const float*)d_in[i + 7];
    const float* b_out = (const float*)d_in[i + 8];
    float* out = (float*)d_out;

    init_kernel<<<512, 256>>>(enc_h, enc_c);
    eproj_kernel<<<dim3(16, 4), 256>>>(emb, W_ih, b_ih, b_hh);
    for (int t = 0; t <= TSTEPS; t++) {
        int tp = (t > 0) ? (t - 1) : 0;
        step_kernel<<<dim3(16, 8), 256>>>(W_hh, W_out, b_out,
                                          out + (size_t)tp * BATCH * VOC, t);
    }
}